// round 13
// baseline (speedup 1.0000x reference)
#include <cuda_runtime.h>

typedef unsigned long long ull;

static constexpr int T_STEPS = 64;
static constexpr int NSIDE = 256;
static constexpr int NPTS = NSIDE * NSIDE;   // 65536
static constexpr int HID = 32;
static constexpr int BLK = 128;
static constexpr float LOG2E = 1.44269504088896340736f;

// Constant bank: layer-0 weights, SECOND half of W1 (cc 16..31), folded
// biases, W2. Flat arrays -> compile-time immediate offsets (LDC.64).
struct CW {
    ull w0r[HID * 6];     // [jj*6+c]: c0..4 = dup(log2e*W0[c][jj]), c5 = dup(log2e*b0[jj])
    ull w1b[HID * 16];    // [jj*16 + (cc-16)] = dup(log2e*W1[cc][jj])
    ull b1[HID];          // dup(log2e*(b1[jj] - sum_c W1[c][jj]))
    ull w2[HID];          // dup(W2[jj])
    float b2;             // b2 - sum_j W2[j]
};
__constant__ CW cw;
__device__ CW g_stage;

__device__ __forceinline__ ull dupf(float v) {
    unsigned u = __float_as_uint(v);
    return (ull)u | ((ull)u << 32);
}

__global__ void prep_kernel(const float* __restrict__ W0, const float* __restrict__ b0,
                            const float* __restrict__ W1, const float* __restrict__ b1,
                            const float* __restrict__ W2, const float* __restrict__ b2) {
    const int tid = threadIdx.x;
    for (int i0 = tid; i0 < HID * 16; i0 += BLK) {
        int jj = i0 >> 4, cc = (i0 & 15) + 16;
        g_stage.w1b[i0] = dupf(LOG2E * W1[cc * HID + jj]);
    }
    for (int i0 = tid; i0 < HID * 6; i0 += BLK) {
        int jj = i0 / 6, c = i0 % 6;
        float v = (c < 5) ? (LOG2E * W0[c * HID + jj]) : (LOG2E * b0[jj]);
        g_stage.w0r[i0] = dupf(v);
    }
    if (tid < HID) {
        float s = 0.0f;
        for (int c = 0; c < HID; c++) s += W1[c * HID + tid];
        g_stage.b1[tid] = dupf(LOG2E * (b1[tid] - s));
        g_stage.w2[tid] = dupf(W2[tid]);
    }
    if (tid == 0) {
        float s = 0.0f;
        for (int jj = 0; jj < HID; jj++) s += W2[jj];
        g_stage.b2 = b2[0] - s;
    }
}

// ---- packed f32x2 helpers (Blackwell FFMA2 only reachable via PTX) ----
__device__ __forceinline__ ull fma2(ull a, ull b, ull c) {
    ull d;
    asm("fma.rn.f32x2 %0, %1, %2, %3;" : "=l"(d) : "l"(a), "l"(b), "l"(c));
    return d;
}
__device__ __forceinline__ ull mul2(ull a, ull b) {
    ull d;
    asm("mul.rn.f32x2 %0, %1, %2;" : "=l"(d) : "l"(a), "l"(b));
    return d;
}
__device__ __forceinline__ ull add2(ull a, ull b) {
    ull d;
    asm("add.rn.f32x2 %0, %1, %2;" : "=l"(d) : "l"(a), "l"(b));
    return d;
}
__device__ __forceinline__ ull pk2(float lo, float hi) {
    ull r;
    asm("mov.b64 %0, {%1, %2};" : "=l"(r) : "f"(lo), "f"(hi));
    return r;
}
__device__ __forceinline__ void upk2(ull v, float& lo, float& hi) {
    asm("mov.b64 {%0, %1}, %2;" : "=f"(lo), "=f"(hi) : "l"(v));
}
__device__ __forceinline__ float ex2f(float v) {
    float r;
    asm("ex2.approx.f32 %0, %1;" : "=f"(r) : "f"(v));
    return r;
}
// preactivation pre-scaled by log2e:  g(v) = elu(v)+1 = max(v',0)*ln2 + ex2(min(v',0))
__device__ __forceinline__ ull g2(ull v) {
    const float LN2 = 0.69314718055994530942f;
    float a, b; upk2(v, a, b);
    float ea = ex2f(fminf(a, 0.0f));
    float eb = ex2f(fminf(b, 0.0f));
    float ha = fmaf(fmaxf(a, 0.0f), LN2, ea);
    float hb = fmaf(fmaxf(b, 0.0f), LN2, eb);
    return pk2(ha, hb);
}

// 2 consecutive points per thread as ONE f32x2 pair. DUAL-PORT weights:
// layer0 + W1 upper half from the constant port, W1 lower half from SMEM.
// Layer-1 processes rows (jj, jj+16) together: 4 independent FMA chains.
__global__ __launch_bounds__(BLK, 4)
void mlpconv_kernel(const float* __restrict__ x,
                    const float* __restrict__ W1,
                    float* __restrict__ out) {
    // sW1a[jj*16+cc] = dup(log2e*W1[cc][jj]) for cc 0..15
    __shared__ __align__(16) ull sW1a[HID * 16];

    const int tid = threadIdx.x;
    for (int i0 = tid; i0 < HID * 16; i0 += BLK) {
        int jj = i0 >> 4, cc = i0 & 15;
        sW1a[i0] = dupf(LOG2E * W1[cc * HID + jj]);
    }
    __syncthreads();

    const int gid = blockIdx.x * BLK + tid;
    const int base = gid * 2;                  // 2 points per thread
    const int t = base >> 16;
    const int p = base & (NPTS - 1);
    const float* xt = x + ((size_t)t << 16);
    const int i = p >> 8;
    const int j = p & 255;                     // even -> pair never crosses a row

    // Stencil (reference's exact wrap semantics)
    const float2 c2 = *reinterpret_cast<const float2*>(xt + p);
    const float2 u2 = *reinterpret_cast<const float2*>(xt + ((p - NSIDE) & (NPTS - 1)));
    const float2 d2 = *reinterpret_cast<const float2*>(xt + ((p + NSIDE) & (NPTS - 1)));
    const float lE = xt[(p - 1) & (NPTS - 1)];
    const float rE = xt[(i << 8) | ((j + 2) & 255)];

    // channel order: l, l2(up), c, r, r2(down); halves = points (0,1)
    const ull pxl = pk2(lE,   c2.x);
    const ull pxu = pk2(u2.x, u2.y);
    const ull pxc = pk2(c2.x, c2.y);
    const ull pxr = pk2(c2.y, rE);
    const ull pxd = pk2(d2.x, d2.y);

    // ---- layer 0: [5] -> [32], weights from constant port, 2 chains ----
    ull h0[HID];
#pragma unroll
    for (int jj = 0; jj < HID; jj++) {
        const ull* r = cw.w0r + jj * 6;
        ull a0 = fma2(pxl, r[0], r[5]);
        ull a1 = mul2(pxu, r[1]);
        a0 = fma2(pxc, r[2], a0);
        a1 = fma2(pxr, r[3], a1);
        a0 = fma2(pxd, r[4], a0);
        h0[jj] = g2(add2(a0, a1));
    }

    // ---- layer 1: rows (jj, jj+16) together; 4 independent chains:
    // SMEM weights drive cc 0..15, constant weights drive cc 16..31.
    ull oA = pk2(cw.b2, cw.b2);
    ull oB = pk2(0.0f, 0.0f);
#pragma unroll
    for (int jj = 0; jj < HID / 2; jj++) {
        const int jB = jj + 16;
        const ulonglong2* rsA = reinterpret_cast<const ulonglong2*>(sW1a + jj * 16);
        const ulonglong2* rsB = reinterpret_cast<const ulonglong2*>(sW1a + jB * 16);
        const ull* rcA = cw.w1b + jj * 16;
        const ull* rcB = cw.w1b + jB * 16;

        ulonglong2 wA = rsA[0];
        ulonglong2 wB = rsB[0];
        ull sA = fma2(h0[0], wA.x, cw.b1[jj]);
        ull sB = fma2(h0[0], wB.x, cw.b1[jB]);
        ull cA = mul2(h0[16], rcA[0]);
        ull cB = mul2(h0[16], rcB[0]);
        sA = fma2(h0[1], wA.y, sA);
        sB = fma2(h0[1], wB.y, sB);
        cA = fma2(h0[17], rcA[1], cA);
        cB = fma2(h0[17], rcB[1], cB);
#pragma unroll
        for (int k = 1; k < 8; k++) {
            wA = rsA[k];
            wB = rsB[k];
            sA = fma2(h0[2 * k],     wA.x, sA);
            sB = fma2(h0[2 * k],     wB.x, sB);
            cA = fma2(h0[16 + 2 * k], rcA[2 * k], cA);
            cB = fma2(h0[16 + 2 * k], rcB[2 * k], cB);
            sA = fma2(h0[2 * k + 1], wA.y, sA);
            sB = fma2(h0[2 * k + 1], wB.y, sB);
            cA = fma2(h0[17 + 2 * k], rcA[2 * k + 1], cA);
            cB = fma2(h0[17 + 2 * k], rcB[2 * k + 1], cB);
        }
        ull aA = g2(add2(sA, cA));
        ull aB = g2(add2(sB, cB));
        oA = fma2(aA, cw.w2[jj], oA);
        oB = fma2(aB, cw.w2[jB], oB);
    }
    ull o = add2(oA, oB);

    float o0, o1;
    upk2(o, o0, o1);
    *reinterpret_cast<float2*>(out + base) = make_float2(o0, o1);
}

extern "C" void kernel_launch(void* const* d_in, const int* in_sizes, int n_in,
                              void* d_out, int out_size) {
    const float* x  = (const float*)d_in[0];
    const float* W0 = (const float*)d_in[1];
    const float* b0 = (const float*)d_in[2];
    const float* W1 = (const float*)d_in[3];
    const float* b1 = (const float*)d_in[4];
    const float* W2 = (const float*)d_in[5];
    const float* b2 = (const float*)d_in[6];
    float* out = (float*)d_out;

    // 1) fold/transform constant-bank weights into staging (device global)
    prep_kernel<<<1, BLK>>>(W0, b0, W1, b1, W2, b2);

    // 2) staging -> constant bank (D2D async memcpy, graph-capturable)
    void* stage_ptr = nullptr;
    cudaGetSymbolAddress(&stage_ptr, g_stage);
    cudaMemcpyToSymbolAsync(cw, stage_ptr, sizeof(CW), 0, cudaMemcpyDeviceToDevice, 0);

    // 3) main kernel (stages SMEM half itself)
    const int total = T_STEPS * NPTS;       // 4194304 points
    const int threads = total / 2;          // 2 points per thread
    mlpconv_kernel<<<threads / BLK, BLK>>>(x, W1, out);
}

// round 14
// speedup vs baseline: 1.2977x; 1.2977x over previous
#include <cuda_runtime.h>

typedef unsigned long long ull;

static constexpr int T_STEPS = 64;
static constexpr int NSIDE = 256;
static constexpr int NPTS = NSIDE * NSIDE;   // 65536
static constexpr int HID = 32;
static constexpr int BLK = 128;
static constexpr float LOG2E = 1.44269504088896340736f;

// Constant bank (MUST stay <= ~4.6KB: larger footprints miss the const cache
// to L2 -- measured cliff R12 vs R10/R11/R13): SECOND half of W1 (cc 16..31),
// folded biases, W2.
struct CW {
    ull w1b[HID * 16];    // [jj*16 + (cc-16)] = dup(log2e*W1[cc][jj])
    ull b1[HID];          // dup(log2e*(b1[jj] - sum_c W1[c][jj]))
    ull w2[HID];          // dup(W2[jj])
    float b2;             // b2 - sum_j W2[j]
};
__constant__ CW cw;
__device__ CW g_stage;

__device__ __forceinline__ ull dupf(float v) {
    unsigned u = __float_as_uint(v);
    return (ull)u | ((ull)u << 32);
}

__global__ void prep_kernel(const float* __restrict__ W1, const float* __restrict__ b1,
                            const float* __restrict__ W2, const float* __restrict__ b2) {
    const int tid = threadIdx.x;
    for (int i0 = tid; i0 < HID * 16; i0 += BLK) {
        int jj = i0 >> 4, cc = (i0 & 15) + 16;
        g_stage.w1b[i0] = dupf(LOG2E * W1[cc * HID + jj]);
    }
    if (tid < HID) {
        float s = 0.0f;
        for (int c = 0; c < HID; c++) s += W1[c * HID + tid];
        g_stage.b1[tid] = dupf(LOG2E * (b1[tid] - s));
        g_stage.w2[tid] = dupf(W2[tid]);
    }
    if (tid == 0) {
        float s = 0.0f;
        for (int jj = 0; jj < HID; jj++) s += W2[jj];
        g_stage.b2 = b2[0] - s;
    }
}

// ---- packed f32x2 helpers (Blackwell FFMA2 only reachable via PTX) ----
__device__ __forceinline__ ull fma2(ull a, ull b, ull c) {
    ull d;
    asm("fma.rn.f32x2 %0, %1, %2, %3;" : "=l"(d) : "l"(a), "l"(b), "l"(c));
    return d;
}
__device__ __forceinline__ ull mul2(ull a, ull b) {
    ull d;
    asm("mul.rn.f32x2 %0, %1, %2;" : "=l"(d) : "l"(a), "l"(b));
    return d;
}
__device__ __forceinline__ ull add2(ull a, ull b) {
    ull d;
    asm("add.rn.f32x2 %0, %1, %2;" : "=l"(d) : "l"(a), "l"(b));
    return d;
}
__device__ __forceinline__ ull pk2(float lo, float hi) {
    ull r;
    asm("mov.b64 %0, {%1, %2};" : "=l"(r) : "f"(lo), "f"(hi));
    return r;
}
__device__ __forceinline__ void upk2(ull v, float& lo, float& hi) {
    asm("mov.b64 {%0, %1}, %2;" : "=f"(lo), "=f"(hi) : "l"(v));
}
__device__ __forceinline__ float ex2f(float v) {
    float r;
    asm("ex2.approx.f32 %0, %1;" : "=f"(r) : "f"(v));
    return r;
}
// preactivation pre-scaled by log2e:  g(v) = elu(v)+1 = max(v',0)*ln2 + ex2(min(v',0))
__device__ __forceinline__ ull g2(ull v) {
    const float LN2 = 0.69314718055994530942f;
    float a, b; upk2(v, a, b);
    float ea = ex2f(fminf(a, 0.0f));
    float eb = ex2f(fminf(b, 0.0f));
    float ha = fmaf(fmaxf(a, 0.0f), LN2, ea);
    float hb = fmaf(fmaxf(b, 0.0f), LN2, eb);
    return pk2(ha, hb);
}

// 2 consecutive points per thread as ONE f32x2 pair. DUAL-PORT weights:
// layer0 + W1 lower half from SMEM (L1 port), W1 upper half + biases from the
// constant bank (constant port, footprint under the const-cache cliff).
// Layer-1 processes rows (jj, jj+16) together: 4 independent FMA chains.
__global__ __launch_bounds__(BLK, 4)
void mlpconv_kernel(const float* __restrict__ x,
                    const float* __restrict__ W0, const float* __restrict__ b0,
                    const float* __restrict__ W1,
                    float* __restrict__ out) {
    // sW0r[jj][0..4] = dup(log2e*W0[c][jj]), [5] = dup(log2e*b0[jj]), pad to 8
    __shared__ __align__(16) ull sW0r[HID * 8];
    // sW1a[jj*16+cc] = dup(log2e*W1[cc][jj]) for cc 0..15
    __shared__ __align__(16) ull sW1a[HID * 16];

    const int tid = threadIdx.x;

    for (int i0 = tid; i0 < HID * 16; i0 += BLK) {
        int jj = i0 >> 4, cc = i0 & 15;
        sW1a[i0] = dupf(LOG2E * W1[cc * HID + jj]);
    }
    for (int i0 = tid; i0 < HID * 8; i0 += BLK) {
        int jj = i0 >> 3, c = i0 & 7;
        float v = 0.0f;
        if (c < 5)       v = LOG2E * W0[c * HID + jj];
        else if (c == 5) v = LOG2E * b0[jj];
        sW0r[i0] = dupf(v);
    }
    __syncthreads();

    const int gid = blockIdx.x * BLK + tid;
    const int base = gid * 2;                  // 2 points per thread
    const int t = base >> 16;
    const int p = base & (NPTS - 1);
    const float* xt = x + ((size_t)t << 16);
    const int i = p >> 8;
    const int j = p & 255;                     // even -> pair never crosses a row

    // Stencil (reference's exact wrap semantics)
    const float2 c2 = *reinterpret_cast<const float2*>(xt + p);
    const float2 u2 = *reinterpret_cast<const float2*>(xt + ((p - NSIDE) & (NPTS - 1)));
    const float2 d2 = *reinterpret_cast<const float2*>(xt + ((p + NSIDE) & (NPTS - 1)));
    const float lE = xt[(p - 1) & (NPTS - 1)];
    const float rE = xt[(i << 8) | ((j + 2) & 255)];

    // channel order: l, l2(up), c, r, r2(down); halves = points (0,1)
    const ull pxl = pk2(lE,   c2.x);
    const ull pxu = pk2(u2.x, u2.y);
    const ull pxc = pk2(c2.x, c2.y);
    const ull pxr = pk2(c2.y, rE);
    const ull pxd = pk2(d2.x, d2.y);

    // ---- layer 0: [5] -> [32], SMEM weights, g-activation (2 chains) ----
    ull h0[HID];
#pragma unroll
    for (int jj = 0; jj < HID; jj++) {
        const ulonglong2* r = reinterpret_cast<const ulonglong2*>(sW0r + jj * 8);
        ulonglong2 w01 = r[0];
        ulonglong2 w23 = r[1];
        ulonglong2 w4b = r[2];
        ull a0 = fma2(pxl, w01.x, w4b.y);
        ull a1 = mul2(pxu, w01.y);
        a0 = fma2(pxc, w23.x, a0);
        a1 = fma2(pxr, w23.y, a1);
        a0 = fma2(pxd, w4b.x, a0);
        h0[jj] = g2(add2(a0, a1));
    }

    // ---- layer 1: rows (jj, jj+16) together; 4 independent chains:
    // SMEM weights drive cc 0..15, constant weights drive cc 16..31.
    ull oA = pk2(cw.b2, cw.b2);
    ull oB = pk2(0.0f, 0.0f);
#pragma unroll
    for (int jj = 0; jj < HID / 2; jj++) {
        const int jB = jj + 16;
        const ulonglong2* rsA = reinterpret_cast<const ulonglong2*>(sW1a + jj * 16);
        const ulonglong2* rsB = reinterpret_cast<const ulonglong2*>(sW1a + jB * 16);
        const ull* rcA = cw.w1b + jj * 16;
        const ull* rcB = cw.w1b + jB * 16;

        ulonglong2 wA = rsA[0];
        ulonglong2 wB = rsB[0];
        ull sA = fma2(h0[0], wA.x, cw.b1[jj]);
        ull sB = fma2(h0[0], wB.x, cw.b1[jB]);
        ull cA = mul2(h0[16], rcA[0]);
        ull cB = mul2(h0[16], rcB[0]);
        sA = fma2(h0[1], wA.y, sA);
        sB = fma2(h0[1], wB.y, sB);
        cA = fma2(h0[17], rcA[1], cA);
        cB = fma2(h0[17], rcB[1], cB);
#pragma unroll
        for (int k = 1; k < 8; k++) {
            wA = rsA[k];
            wB = rsB[k];
            sA = fma2(h0[2 * k],      wA.x,           sA);
            sB = fma2(h0[2 * k],      wB.x,           sB);
            cA = fma2(h0[16 + 2 * k], rcA[2 * k],     cA);
            cB = fma2(h0[16 + 2 * k], rcB[2 * k],     cB);
            sA = fma2(h0[2 * k + 1],  wA.y,           sA);
            sB = fma2(h0[2 * k + 1],  wB.y,           sB);
            cA = fma2(h0[17 + 2 * k], rcA[2 * k + 1], cA);
            cB = fma2(h0[17 + 2 * k], rcB[2 * k + 1], cB);
        }
        ull aA = g2(add2(sA, cA));
        ull aB = g2(add2(sB, cB));
        oA = fma2(aA, cw.w2[jj], oA);
        oB = fma2(aB, cw.w2[jB], oB);
    }
    ull o = add2(oA, oB);

    float o0, o1;
    upk2(o, o0, o1);
    *reinterpret_cast<float2*>(out + base) = make_float2(o0, o1);
}

extern "C" void kernel_launch(void* const* d_in, const int* in_sizes, int n_in,
                              void* d_out, int out_size) {
    const float* x  = (const float*)d_in[0];
    const float* W0 = (const float*)d_in[1];
    const float* b0 = (const float*)d_in[2];
    const float* W1 = (const float*)d_in[3];
    const float* b1 = (const float*)d_in[4];
    const float* W2 = (const float*)d_in[5];
    const float* b2 = (const float*)d_in[6];
    float* out = (float*)d_out;

    // 1) fold/transform the constant-bank half into staging (device global)
    prep_kernel<<<1, BLK>>>(W1, b1, W2, b2);

    // 2) staging -> constant bank (D2D async memcpy, graph-capturable)
    void* stage_ptr = nullptr;
    cudaGetSymbolAddress(&stage_ptr, g_stage);
    cudaMemcpyToSymbolAsync(cw, stage_ptr, sizeof(CW), 0, cudaMemcpyDeviceToDevice, 0);

    // 3) main kernel (stages SMEM halves itself)
    const int total = T_STEPS * NPTS;       // 4194304 points
    const int threads = total / 2;          // 2 points per thread
    mlpconv_kernel<<<threads / BLK, BLK>>>(x, W0, b0, W1, out);
}